// round 6
// baseline (speedup 1.0000x reference)
#include <cuda_runtime.h>
#include <math.h>
#include <stdint.h>

// ---------------------------------------------------------------------------
// SwitchHeadCore: B=2,S=2048,D=1024,H=8,E=4,K=2,DH=128
// router -> transpose(Wv,Wo) -> 512-thread 256x256 tf32 mma GEMMs
// (merged q/k proj, dense v-all, gated out) + vgate + tf32 flash attention.
// ---------------------------------------------------------------------------

#define B_ 2
#define S_ 2048
#define D_ 1024
#define H_ 8
#define E_ 4
#define DH_ 128
#define TOK_ (B_ * S_)              // 4096
#define GE_ (H_ * E_)               // 32
#define KEXP_ 4096                  // H*E*DH

__device__ float g_q[TOK_ * D_];     // [B,H,S,DH]
__device__ float g_k[TOK_ * D_];
__device__ float g_v[TOK_ * D_];
__device__ float g_res[TOK_ * D_];
__device__ float g_gv[TOK_ * GE_];
__device__ float g_go[TOK_ * GE_];
__device__ float g_yall[(size_t)TOK_ * KEXP_];  // all-expert V outputs
__device__ float g_wvT[(size_t)KEXP_ * D_];     // [(h,e,dh), d]
__device__ float g_woT[(size_t)D_ * KEXP_];     // [o, (h,e,dh)]

// ============================ mma helpers ==================================
__device__ __forceinline__ uint32_t f2tf32(float f) {
    uint32_t u;
    asm("cvt.rna.tf32.f32 %0, %1;" : "=r"(u) : "f"(f));
    return u;
}
__device__ __forceinline__ void mma_tf32(float* d, const uint32_t* a, const uint32_t* b) {
    asm volatile(
        "mma.sync.aligned.m16n8k8.row.col.f32.tf32.tf32.f32 "
        "{%0,%1,%2,%3}, {%4,%5,%6,%7}, {%8,%9}, {%0,%1,%2,%3};\n"
        : "+f"(d[0]), "+f"(d[1]), "+f"(d[2]), "+f"(d[3])
        : "r"(a[0]), "r"(a[1]), "r"(a[2]), "r"(a[3]), "r"(b[0]), "r"(b[1]));
}

// ============================ router =======================================
__global__ void router_kernel(const float* __restrict__ q_src,
                              const float* __restrict__ k_src,
                              const float* __restrict__ sel_v,
                              const float* __restrict__ sel_o) {
    int t = blockIdx.x;
    int tid = threadIdx.x;
    __shared__ float xs[D_];
    __shared__ float sg[GE_];

    for (int r = 0; r < 2; r++) {
        const float* src = (r == 0) ? k_src : q_src;
        const float* sel = (r == 0) ? sel_v : sel_o;
        float* gout      = (r == 0) ? g_gv  : g_go;

        for (int i = tid; i < D_ / 4; i += blockDim.x)
            ((float4*)xs)[i] = ((const float4*)(src + (size_t)t * D_))[i];
        __syncthreads();

        int g = tid >> 3;
        int l8 = tid & 7;
        const float* w = sel + (size_t)g * D_;
        float sum = 0.f;
        for (int d = l8; d < D_; d += 8) sum += xs[d] * w[d];
        sum += __shfl_xor_sync(0xffffffffu, sum, 1);
        sum += __shfl_xor_sync(0xffffffffu, sum, 2);
        sum += __shfl_xor_sync(0xffffffffu, sum, 4);
        if (l8 == 0) sg[g] = 1.f / (1.f + __expf(-sum));
        __syncthreads();

        if (tid < H_) {
            int h = tid;
            float vals[4];
            #pragma unroll
            for (int e = 0; e < 4; e++) vals[e] = sg[h * 4 + e];
            int i1 = 0;
            #pragma unroll
            for (int e = 1; e < 4; e++) if (vals[e] > vals[i1]) i1 = e;
            int i2 = -1;
            #pragma unroll
            for (int e = 0; e < 4; e++) {
                if (e == i1) continue;
                if (i2 < 0 || vals[e] > vals[i2]) i2 = e;
            }
            #pragma unroll
            for (int e = 0; e < 4; e++)
                gout[(size_t)t * GE_ + h * 4 + e] = (e == i1 || e == i2) ? vals[e] : 0.f;
        }
        __syncthreads();
    }
}

// ============================ transpose ====================================
__global__ void transpose_kernel(const float* __restrict__ src, float* __restrict__ dst,
                                 int R, int C) {
    __shared__ float tile[32][33];
    size_t zo = (size_t)blockIdx.z * R * C;
    src += zo; dst += zo;
    int r0 = blockIdx.y * 32, c0 = blockIdx.x * 32;
    int x = threadIdx.x, y = threadIdx.y;
    #pragma unroll
    for (int i = 0; i < 32; i += 8)
        tile[y + i][x] = src[(size_t)(r0 + y + i) * C + c0 + x];
    __syncthreads();
    #pragma unroll
    for (int i = 0; i < 32; i += 8)
        dst[(size_t)(c0 + y + i) * R + r0 + x] = tile[x][y + i];
}

// ============================ tf32 mma GEMM ================================
// C[M,N] = alpha * A @ B^T.  Block 256x256xBK32, 512 threads, 16 warps (4x4),
// warp tile 64x64 (4 mi x 8 ni m16n8k8).  PAD 36.  Double buffered dyn SMEM.
// MODE 0: row-major C.
// MODE 1: merged q/k proj; blockIdx.z picks (A,B,C); C layout [B,H,S,DH].
// MODE 2: A = g_go-gated expansion of g_res (A ptr = g_res), C row-major.
#define PAD_ 36
#define GBUF_ (2 * 256 * PAD_)          // words per buffer (As+Bs)
#define GSMEM_BYTES (2 * GBUF_ * 4)     // 147456

template<int MODE>
__global__ __launch_bounds__(512) void gemm_tf32(const float* __restrict__ A,
                                                 const float* __restrict__ B,
                                                 float* __restrict__ C,
                                                 int Ktot, int ldc, float alpha,
                                                 const float* __restrict__ A2,
                                                 const float* __restrict__ B2,
                                                 float* __restrict__ C2) {
    extern __shared__ __align__(16) uint32_t dsm[];

    int tid = threadIdx.x;
    int wid = tid >> 5;
    int lane = tid & 31;
    int m0 = blockIdx.y * 256, n0 = blockIdx.x * 256;
    int m0w = (wid >> 2) * 64, n0w = (wid & 3) * 64;

    if (MODE == 1 && blockIdx.z == 1) { A = A2; B = B2; C = C2; }

    int row = tid >> 1, half = tid & 1;         // 256 rows, 16 floats each
    const float* Ap = A + (size_t)(m0 + row) * Ktot + half * 16;
    const float* Bp = B + (size_t)(n0 + row) * Ktot + half * 16;
    uint32_t sts_off = (uint32_t)(row * PAD_ + half * 16);

    // MODE 2 addressing
    int t2 = m0 + row;
    int bb2 = t2 >> 11, ss2 = t2 & (S_ - 1);
    const float* Rbase = A + (((size_t)bb2 * H_) * S_ + ss2) * DH_;
    const float* Gp2 = g_go + (size_t)t2 * GE_;

    float acc[4][8][4];
    #pragma unroll
    for (int i = 0; i < 4; i++)
        #pragma unroll
        for (int j = 0; j < 8; j++)
            #pragma unroll
            for (int c = 0; c < 4; c++) acc[i][j][c] = 0.f;

    int KT = Ktot >> 5;
    float4 ra[4], rb[4];

    auto loadAB = [&](int kt) {
        if (MODE == 2) {
            #pragma unroll
            for (int j = 0; j < 4; j++) {
                int k = kt * 32 + half * 16 + j * 4;
                int he = k >> 7;
                int dh = k & 127;
                float4 v = *(const float4*)(Rbase + (size_t)(he >> 2) * S_ * DH_ + dh);
                float g = Gp2[he];
                v.x *= g; v.y *= g; v.z *= g; v.w *= g;
                ra[j] = v;
            }
        } else {
            #pragma unroll
            for (int j = 0; j < 4; j++)
                ra[j] = *(const float4*)(Ap + kt * 32 + j * 4);
        }
        #pragma unroll
        for (int j = 0; j < 4; j++)
            rb[j] = *(const float4*)(Bp + kt * 32 + j * 4);
    };
    auto stage = [&](int s) {
        uint32_t* As = dsm + s * GBUF_;
        uint32_t* Bs = As + 256 * PAD_;
        #pragma unroll
        for (int j = 0; j < 4; j++) {
            uint4 ua = make_uint4(f2tf32(ra[j].x), f2tf32(ra[j].y), f2tf32(ra[j].z), f2tf32(ra[j].w));
            uint4 ub = make_uint4(f2tf32(rb[j].x), f2tf32(rb[j].y), f2tf32(rb[j].z), f2tf32(rb[j].w));
            *(uint4*)&As[sts_off + j * 4] = ua;
            *(uint4*)&Bs[sts_off + j * 4] = ub;
        }
    };

    loadAB(0);
    stage(0);
    __syncthreads();

    int r4 = lane >> 2, c4 = lane & 3;

    for (int kt = 0; kt < KT; kt++) {
        if (kt + 1 < KT) loadAB(kt + 1);

        uint32_t* As = dsm + (kt & 1) * GBUF_;
        uint32_t* Bs = As + 256 * PAD_;
        #pragma unroll
        for (int ks = 0; ks < 4; ks++) {
            int kb = ks * 8;
            uint32_t a[4][4], b[8][2];
            #pragma unroll
            for (int mi = 0; mi < 4; mi++) {
                int rr = (m0w + mi * 16 + r4) * PAD_ + kb + c4;
                a[mi][0] = As[rr];
                a[mi][1] = As[rr + 8 * PAD_];
                a[mi][2] = As[rr + 4];
                a[mi][3] = As[rr + 8 * PAD_ + 4];
            }
            #pragma unroll
            for (int ni = 0; ni < 8; ni++) {
                int rr = (n0w + ni * 8 + r4) * PAD_ + kb + c4;
                b[ni][0] = Bs[rr];
                b[ni][1] = Bs[rr + 4];
            }
            #pragma unroll
            for (int mi = 0; mi < 4; mi++)
                #pragma unroll
                for (int ni = 0; ni < 8; ni++)
                    mma_tf32(acc[mi][ni], a[mi], b[ni]);
        }

        if (kt + 1 < KT) {
            stage((kt + 1) & 1);
            __syncthreads();
        }
    }

    #pragma unroll
    for (int mi = 0; mi < 4; mi++) {
        #pragma unroll
        for (int half_m = 0; half_m < 2; half_m++) {
            int m = m0 + m0w + mi * 16 + half_m * 8 + r4;
            int bb = m >> 11, ss = m & (S_ - 1);
            #pragma unroll
            for (int ni = 0; ni < 8; ni++) {
                int n = n0 + n0w + ni * 8 + c4 * 2;
                float2 o;
                o.x = acc[mi][ni][half_m * 2 + 0] * alpha;
                o.y = acc[mi][ni][half_m * 2 + 1] * alpha;
                if (MODE == 1) {
                    int h = n >> 7, dh = n & 127;
                    *(float2*)(C + (((size_t)bb * H_ + h) * S_ + ss) * DH_ + dh) = o;
                } else {
                    *(float2*)(C + (size_t)m * ldc + n) = o;
                }
            }
        }
    }
}

// ============================ gated reduce (V) =============================
__global__ __launch_bounds__(256) void vgate_kernel() {
    int idx = blockIdx.x * 256 + threadIdx.x;   // 4096*8*32
    int dh4 = idx & 31;
    int h = (idx >> 5) & 7;
    int t = idx >> 8;
    int b = t >> 11, s = t & (S_ - 1);
    const float* y = g_yall + (size_t)t * KEXP_ + h * 512 + dh4 * 4;
    const float* g = g_gv + (size_t)t * GE_ + h * 4;
    float4 acc = make_float4(0.f, 0.f, 0.f, 0.f);
    #pragma unroll
    for (int e = 0; e < 4; e++) {
        float ge = g[e];
        float4 ye = *(const float4*)(y + e * 128);
        acc.x += ge * ye.x; acc.y += ge * ye.y; acc.z += ge * ye.z; acc.w += ge * ye.w;
    }
    *(float4*)&g_v[(((size_t)b * H_ + h) * S_ + s) * DH_ + dh4 * 4] = acc;
}

// ============================ tf32 flash attention =========================
// q tile 128 (8 warps x 16 rows), kv tile 64, K/V register prefetch.
#define QP_ 132
#define VP_ 68
#define ATTN_SMEM ((128 * QP_ + 64 * QP_ + 128 * VP_ + 128 * VP_) * 4)

__global__ __launch_bounds__(256) void attn_tc_kernel() {
    extern __shared__ __align__(16) uint32_t asm_[];
    uint32_t* Qs = asm_;
    uint32_t* Ks = Qs + 128 * QP_;
    uint32_t* Vt = Ks + 64 * QP_;
    uint32_t* Ps = Vt + 128 * VP_;

    int bh = blockIdx.y;
    int q0 = blockIdx.x * 128;
    const float* Qg = g_q + (size_t)bh * S_ * DH_;
    const float* Kg = g_k + (size_t)bh * S_ * DH_;
    const float* Vg = g_v + (size_t)bh * S_ * DH_;

    int tid = threadIdx.x;
    int wid = tid >> 5;
    int lane = tid & 31;
    int r4 = lane >> 2, c4 = lane & 3;
    int m0w = wid * 16;

    for (int i = tid; i < 128 * 32; i += 256) {
        int r = i >> 5, c = (i & 31) * 4;
        float4 v = *(const float4*)(Qg + (size_t)(q0 + r) * DH_ + c);
        uint4 u = make_uint4(f2tf32(v.x), f2tf32(v.y), f2tf32(v.z), f2tf32(v.w));
        *(uint4*)&Qs[r * QP_ + c] = u;
    }

    float4 kreg[8], vreg[8];
    auto loadK = [&](int j0) {
        #pragma unroll
        for (int j = 0; j < 8; j++) {
            int i = tid + 256 * j;
            int r = i >> 5, c = (i & 31) * 4;
            kreg[j] = *(const float4*)(Kg + (size_t)(j0 + r) * DH_ + c);
        }
    };
    auto loadV = [&](int j0) {
        #pragma unroll
        for (int j = 0; j < 8; j++) {
            int i = tid + 256 * j;
            int r = i & 63, c = (i >> 6) * 4;
            vreg[j] = *(const float4*)(Vg + (size_t)(j0 + r) * DH_ + c);
        }
    };

    loadK(0);
    loadV(0);

    float o[16][4];
    #pragma unroll
    for (int ni = 0; ni < 16; ni++)
        #pragma unroll
        for (int c = 0; c < 4; c++) o[ni][c] = 0.f;
    float mA = -1e30f, mB = -1e30f, lA = 0.f, lB = 0.f;

    for (int j0 = 0; j0 < S_; j0 += 64) {
        __syncthreads();
        #pragma unroll
        for (int j = 0; j < 8; j++) {
            int i = tid + 256 * j;
            int r = i >> 5, c = (i & 31) * 4;
            uint4 u = make_uint4(f2tf32(kreg[j].x), f2tf32(kreg[j].y),
                                 f2tf32(kreg[j].z), f2tf32(kreg[j].w));
            *(uint4*)&Ks[r * QP_ + c] = u;
        }
        #pragma unroll
        for (int j = 0; j < 8; j++) {
            int i = tid + 256 * j;
            int r = i & 63, c = (i >> 6) * 4;
            Vt[(c + 0) * VP_ + r] = f2tf32(vreg[j].x);
            Vt[(c + 1) * VP_ + r] = f2tf32(vreg[j].y);
            Vt[(c + 2) * VP_ + r] = f2tf32(vreg[j].z);
            Vt[(c + 3) * VP_ + r] = f2tf32(vreg[j].w);
        }
        __syncthreads();

        bool more = (j0 + 64) < S_;
        if (more) loadK(j0 + 64);

        float sf[8][4];
        #pragma unroll
        for (int ni = 0; ni < 8; ni++)
            #pragma unroll
            for (int c = 0; c < 4; c++) sf[ni][c] = 0.f;

        #pragma unroll
        for (int ks = 0; ks < 16; ks++) {
            int kb = ks * 8;
            uint32_t a[4];
            int ar = (m0w + r4) * QP_ + kb + c4;
            a[0] = Qs[ar];
            a[1] = Qs[ar + 8 * QP_];
            a[2] = Qs[ar + 4];
            a[3] = Qs[ar + 8 * QP_ + 4];
            #pragma unroll
            for (int ni = 0; ni < 8; ni++) {
                uint32_t b[2];
                int br = (ni * 8 + r4) * QP_ + kb + c4;
                b[0] = Ks[br];
                b[1] = Ks[br + 4];
                mma_tf32(sf[ni], a, b);
            }
        }

        if (more) loadV(j0 + 64);

        float mxA = -1e30f, mxB = -1e30f;
        #pragma unroll
        for (int ni = 0; ni < 8; ni++) {
            mxA = fmaxf(mxA, fmaxf(sf[ni][0], sf[ni][1]));
            mxB = fmaxf(mxB, fmaxf(sf[ni][2], sf[ni][3]));
        }
        mxA = fmaxf(mxA, __shfl_xor_sync(0xffffffffu, mxA, 1));
        mxA = fmaxf(mxA, __shfl_xor_sync(0xffffffffu, mxA, 2));
        mxB = fmaxf(mxB, __shfl_xor_sync(0xffffffffu, mxB, 1));
        mxB = fmaxf(mxB, __shfl_xor_sync(0xffffffffu, mxB, 2));
        float mnA = fmaxf(mA, mxA), mnB = fmaxf(mB, mxB);
        float scA = __expf(mA - mnA), scB = __expf(mB - mnB);
        float sA = 0.f, sB = 0.f;
        int prA = (m0w + r4) * VP_;
        int prB = prA + 8 * VP_;
        #pragma unroll
        for (int ni = 0; ni < 8; ni++) {
            float e0 = __expf(sf[ni][0] - mnA);
            float e1 = __expf(sf[ni][1] - mnA);
            float e2 = __expf(sf[ni][2] - mnB);
            float e3 = __expf(sf[ni][3] - mnB);
            sA += e0 + e1; sB += e2 + e3;
            int cc = ni * 8 + c4 * 2;
            Ps[prA + cc] = f2tf32(e0); Ps[prA + cc + 1] = f2tf32(e1);
            Ps[prB + cc] = f2tf32(e2); Ps[prB + cc + 1] = f2tf32(e3);
        }
        sA += __shfl_xor_sync(0xffffffffu, sA, 1);
        sA += __shfl_xor_sync(0xffffffffu, sA, 2);
        sB += __shfl_xor_sync(0xffffffffu, sB, 1);
        sB += __shfl_xor_sync(0xffffffffu, sB, 2);
        lA = lA * scA + sA; lB = lB * scB + sB;
        mA = mnA; mB = mnB;
        #pragma unroll
        for (int ni = 0; ni < 16; ni++) {
            o[ni][0] *= scA; o[ni][1] *= scA;
            o[ni][2] *= scB; o[ni][3] *= scB;
        }
        __syncwarp();

        #pragma unroll
        for (int ks = 0; ks < 8; ks++) {
            int kb = ks * 8;
            uint32_t a[4];
            int ar = (m0w + r4) * VP_ + kb + c4;
            a[0] = Ps[ar];
            a[1] = Ps[ar + 8 * VP_];
            a[2] = Ps[ar + 4];
            a[3] = Ps[ar + 8 * VP_ + 4];
            #pragma unroll
            for (int ni = 0; ni < 16; ni++) {
                uint32_t b[2];
                int br = (ni * 8 + r4) * VP_ + kb + c4;
                b[0] = Vt[br];
                b[1] = Vt[br + 4];
                mma_tf32(o[ni], a, b);
            }
        }
    }

    float invA = 1.f / lA, invB = 1.f / lB;
    int rA = q0 + m0w + r4;
    float* OgA = g_res + (size_t)bh * S_ * DH_ + (size_t)rA * DH_;
    float* OgB = OgA + 8 * DH_;
    #pragma unroll
    for (int ni = 0; ni < 16; ni++) {
        int cc = ni * 8 + c4 * 2;
        float2 oa, ob;
        oa.x = o[ni][0] * invA; oa.y = o[ni][1] * invA;
        ob.x = o[ni][2] * invB; ob.y = o[ni][3] * invB;
        *(float2*)(OgA + cc) = oa;
        *(float2*)(OgB + cc) = ob;
    }
}

// ---------------------------------------------------------------------------
extern "C" void kernel_launch(void* const* d_in, const int* in_sizes, int n_in,
                              void* d_out, int out_size) {
    const float* q_src = (const float*)d_in[0];
    const float* k_src = (const float*)d_in[1];
    const float* v_src = (const float*)d_in[2];
    const float* Wq    = (const float*)d_in[3];
    const float* Wk    = (const float*)d_in[4];
    const float* Wv    = (const float*)d_in[5];
    const float* Wo    = (const float*)d_in[6];
    const float* sel_v = (const float*)d_in[7];
    const float* sel_o = (const float*)d_in[8];
    float* outp = (float*)d_out;

    cudaFuncSetAttribute(attn_tc_kernel, cudaFuncAttributeMaxDynamicSharedMemorySize, ATTN_SMEM);
    cudaFuncSetAttribute(gemm_tf32<0>, cudaFuncAttributeMaxDynamicSharedMemorySize, GSMEM_BYTES);
    cudaFuncSetAttribute(gemm_tf32<1>, cudaFuncAttributeMaxDynamicSharedMemorySize, GSMEM_BYTES);
    cudaFuncSetAttribute(gemm_tf32<2>, cudaFuncAttributeMaxDynamicSharedMemorySize, GSMEM_BYTES);

    float *gq, *gk, *gyall, *gwvT, *gwoT, *gres;
    cudaGetSymbolAddress((void**)&gq, g_q);
    cudaGetSymbolAddress((void**)&gk, g_k);
    cudaGetSymbolAddress((void**)&gyall, g_yall);
    cudaGetSymbolAddress((void**)&gwvT, g_wvT);
    cudaGetSymbolAddress((void**)&gwoT, g_woT);
    cudaGetSymbolAddress((void**)&gres, g_res);

    const float scale = 0.29730177875068026f;  // 128^-0.25

    router_kernel<<<TOK_, 256>>>(q_src, k_src, sel_v, sel_o);

    // Wv [H,E,D,DH] -> WvT [(h,e,dh), d]
    transpose_kernel<<<dim3(DH_ / 32, D_ / 32, GE_), dim3(32, 8)>>>(Wv, gwvT, D_, DH_);
    // Wo flat [(h,e,dh), o] -> WoT [o, (h,e,dh)]
    transpose_kernel<<<dim3(D_ / 32, KEXP_ / 32, 1), dim3(32, 8)>>>(Wo, gwoT, KEXP_, D_);

    // merged q/k projections: M=4096, N=1024, K=1024; z=0 -> q, z=1 -> k
    gemm_tf32<1><<<dim3(D_ / 256, TOK_ / 256, 2), 512, GSMEM_BYTES>>>(
        q_src, Wq, gq, D_, 0, scale, k_src, Wk, gk);

    // all-expert V: M=4096, N=4096, K=1024
    gemm_tf32<0><<<dim3(KEXP_ / 256, TOK_ / 256), 512, GSMEM_BYTES>>>(
        v_src, gwvT, gyall, D_, KEXP_, 1.0f, nullptr, nullptr, nullptr);
    vgate_kernel<<<TOK_ * H_ * 32 / 256, 256>>>();

    attn_tc_kernel<<<dim3(S_ / 128, B_ * H_), 256, ATTN_SMEM>>>();

    // out: M=4096, N=1024, K=4096, A = gated g_res expansion (MODE 2)
    gemm_tf32<2><<<dim3(D_ / 256, TOK_ / 256), 512, GSMEM_BYTES>>>(
        gres, gwoT, outp, KEXP_, D_, 1.0f, nullptr, nullptr, nullptr);
}

// round 7
// speedup vs baseline: 8.1543x; 8.1543x over previous
#include <cuda_runtime.h>
#include <math.h>
#include <stdint.h>

// ---------------------------------------------------------------------------
// SwitchHeadCore: B=2,S=2048,D=1024,H=8,E=4,K=2,DH=128
// router -> transpose(Wv,Wo) -> 256-thread 128x256 tf32 mma GEMMs (warp 64x64)
// (merged q/k proj, dense v-all, gated out) + vgate + tf32 flash attention.
// ---------------------------------------------------------------------------

#define B_ 2
#define S_ 2048
#define D_ 1024
#define H_ 8
#define E_ 4
#define DH_ 128
#define TOK_ (B_ * S_)              // 4096
#define GE_ (H_ * E_)               // 32
#define KEXP_ 4096                  // H*E*DH

__device__ float g_q[TOK_ * D_];     // [B,H,S,DH]
__device__ float g_k[TOK_ * D_];
__device__ float g_v[TOK_ * D_];
__device__ float g_res[TOK_ * D_];
__device__ float g_gv[TOK_ * GE_];
__device__ float g_go[TOK_ * GE_];
__device__ float g_yall[(size_t)TOK_ * KEXP_];  // all-expert V outputs
__device__ float g_wvT[(size_t)KEXP_ * D_];     // [(h,e,dh), d]
__device__ float g_woT[(size_t)D_ * KEXP_];     // [o, (h,e,dh)]

// ============================ mma helpers ==================================
__device__ __forceinline__ uint32_t f2tf32(float f) {
    uint32_t u;
    asm("cvt.rna.tf32.f32 %0, %1;" : "=r"(u) : "f"(f));
    return u;
}
__device__ __forceinline__ void mma_tf32(float* d, const uint32_t* a, const uint32_t* b) {
    asm volatile(
        "mma.sync.aligned.m16n8k8.row.col.f32.tf32.tf32.f32 "
        "{%0,%1,%2,%3}, {%4,%5,%6,%7}, {%8,%9}, {%0,%1,%2,%3};\n"
        : "+f"(d[0]), "+f"(d[1]), "+f"(d[2]), "+f"(d[3])
        : "r"(a[0]), "r"(a[1]), "r"(a[2]), "r"(a[3]), "r"(b[0]), "r"(b[1]));
}

// ============================ router =======================================
__global__ void router_kernel(const float* __restrict__ q_src,
                              const float* __restrict__ k_src,
                              const float* __restrict__ sel_v,
                              const float* __restrict__ sel_o) {
    int t = blockIdx.x;
    int tid = threadIdx.x;
    __shared__ float xs[D_];
    __shared__ float sg[GE_];

    for (int r = 0; r < 2; r++) {
        const float* src = (r == 0) ? k_src : q_src;
        const float* sel = (r == 0) ? sel_v : sel_o;
        float* gout      = (r == 0) ? g_gv  : g_go;

        for (int i = tid; i < D_ / 4; i += blockDim.x)
            ((float4*)xs)[i] = ((const float4*)(src + (size_t)t * D_))[i];
        __syncthreads();

        int g = tid >> 3;
        int l8 = tid & 7;
        const float* w = sel + (size_t)g * D_;
        float sum = 0.f;
        for (int d = l8; d < D_; d += 8) sum += xs[d] * w[d];
        sum += __shfl_xor_sync(0xffffffffu, sum, 1);
        sum += __shfl_xor_sync(0xffffffffu, sum, 2);
        sum += __shfl_xor_sync(0xffffffffu, sum, 4);
        if (l8 == 0) sg[g] = 1.f / (1.f + __expf(-sum));
        __syncthreads();

        if (tid < H_) {
            int h = tid;
            float vals[4];
            #pragma unroll
            for (int e = 0; e < 4; e++) vals[e] = sg[h * 4 + e];
            int i1 = 0;
            #pragma unroll
            for (int e = 1; e < 4; e++) if (vals[e] > vals[i1]) i1 = e;
            int i2 = -1;
            #pragma unroll
            for (int e = 0; e < 4; e++) {
                if (e == i1) continue;
                if (i2 < 0 || vals[e] > vals[i2]) i2 = e;
            }
            #pragma unroll
            for (int e = 0; e < 4; e++)
                gout[(size_t)t * GE_ + h * 4 + e] = (e == i1 || e == i2) ? vals[e] : 0.f;
        }
        __syncthreads();
    }
}

// ============================ transpose ====================================
__global__ void transpose_kernel(const float* __restrict__ src, float* __restrict__ dst,
                                 int R, int C) {
    __shared__ float tile[32][33];
    size_t zo = (size_t)blockIdx.z * R * C;
    src += zo; dst += zo;
    int r0 = blockIdx.y * 32, c0 = blockIdx.x * 32;
    int x = threadIdx.x, y = threadIdx.y;
    #pragma unroll
    for (int i = 0; i < 32; i += 8)
        tile[y + i][x] = src[(size_t)(r0 + y + i) * C + c0 + x];
    __syncthreads();
    #pragma unroll
    for (int i = 0; i < 32; i += 8)
        dst[(size_t)(c0 + y + i) * R + r0 + x] = tile[x][y + i];
}

// ============================ tf32 mma GEMM ================================
// C[M,N] = alpha * A @ B^T.  Block 128x256xBK32, 256 threads, 8 warps (2m x 4n),
// warp tile 64x64 (4 mi x 8 ni m16n8k8).  PAD 36.  Double-buffered dyn SMEM.
// MODE 0: row-major C.
// MODE 1: merged q/k proj; blockIdx.z picks (A,B,C); C layout [B,H,S,DH].
// MODE 2: A = g_go-gated expansion of g_res (A ptr = g_res), C row-major.
#define PAD_ 36
#define ABUF_ (128 * PAD_)
#define BBUF_ (256 * PAD_)
#define GBUF_ (ABUF_ + BBUF_)           // words per buffer
#define GSMEM_BYTES (2 * GBUF_ * 4)     // 110592

template<int MODE>
__global__ __launch_bounds__(256) void gemm_tf32(const float* __restrict__ A,
                                                 const float* __restrict__ B,
                                                 float* __restrict__ C,
                                                 int Ktot, int ldc, float alpha,
                                                 const float* __restrict__ A2,
                                                 const float* __restrict__ B2,
                                                 float* __restrict__ C2) {
    extern __shared__ __align__(16) uint32_t dsm[];

    int tid = threadIdx.x;
    int wid = tid >> 5;
    int lane = tid & 31;
    int m0 = blockIdx.y * 128, n0 = blockIdx.x * 256;
    int m0w = (wid >> 2) * 64, n0w = (wid & 3) * 64;

    if (MODE == 1 && blockIdx.z == 1) { A = A2; B = B2; C = C2; }

    // A loader: 2 threads/row (128 rows), 16 floats each
    int arow = tid >> 1, ahalf = tid & 1;
    const float* Ap = A + (size_t)(m0 + arow) * Ktot + ahalf * 16;
    uint32_t a_sts = (uint32_t)(arow * PAD_ + ahalf * 16);
    // B loader: 1 thread/row (256 rows), 32 floats each
    const float* Bp = B + (size_t)(n0 + tid) * Ktot;
    uint32_t b_sts = (uint32_t)(tid * PAD_);

    // MODE 2 addressing (A rows are tokens)
    int t2 = m0 + arow;
    int bb2 = t2 >> 11, ss2 = t2 & (S_ - 1);
    const float* Rbase = A + (((size_t)bb2 * H_) * S_ + ss2) * DH_;
    const float* Gp2 = g_go + (size_t)t2 * GE_;

    float acc[4][8][4];
    #pragma unroll
    for (int i = 0; i < 4; i++)
        #pragma unroll
        for (int j = 0; j < 8; j++)
            #pragma unroll
            for (int c = 0; c < 4; c++) acc[i][j][c] = 0.f;

    int KT = Ktot >> 5;
    float4 ra[4], rb[8];

    auto loadAB = [&](int kt) {
        if (MODE == 2) {
            #pragma unroll
            for (int j = 0; j < 4; j++) {
                int k = kt * 32 + ahalf * 16 + j * 4;
                int he = k >> 7;
                int dh = k & 127;
                float4 v = *(const float4*)(Rbase + (size_t)(he >> 2) * S_ * DH_ + dh);
                float g = Gp2[he];
                v.x *= g; v.y *= g; v.z *= g; v.w *= g;
                ra[j] = v;
            }
        } else {
            #pragma unroll
            for (int j = 0; j < 4; j++)
                ra[j] = *(const float4*)(Ap + kt * 32 + j * 4);
        }
        #pragma unroll
        for (int j = 0; j < 8; j++)
            rb[j] = *(const float4*)(Bp + kt * 32 + j * 4);
    };
    auto stage = [&](int s) {
        uint32_t* As = dsm + s * GBUF_;
        uint32_t* Bs = As + ABUF_;
        #pragma unroll
        for (int j = 0; j < 4; j++) {
            uint4 ua = make_uint4(f2tf32(ra[j].x), f2tf32(ra[j].y), f2tf32(ra[j].z), f2tf32(ra[j].w));
            *(uint4*)&As[a_sts + j * 4] = ua;
        }
        #pragma unroll
        for (int j = 0; j < 8; j++) {
            uint4 ub = make_uint4(f2tf32(rb[j].x), f2tf32(rb[j].y), f2tf32(rb[j].z), f2tf32(rb[j].w));
            *(uint4*)&Bs[b_sts + j * 4] = ub;
        }
    };

    loadAB(0);
    stage(0);
    __syncthreads();

    int r4 = lane >> 2, c4 = lane & 3;

    for (int kt = 0; kt < KT; kt++) {
        if (kt + 1 < KT) loadAB(kt + 1);

        uint32_t* As = dsm + (kt & 1) * GBUF_;
        uint32_t* Bs = As + ABUF_;
        #pragma unroll
        for (int ks = 0; ks < 4; ks++) {
            int kb = ks * 8;
            uint32_t a[4][4], b[8][2];
            #pragma unroll
            for (int mi = 0; mi < 4; mi++) {
                int rr = (m0w + mi * 16 + r4) * PAD_ + kb + c4;
                a[mi][0] = As[rr];
                a[mi][1] = As[rr + 8 * PAD_];
                a[mi][2] = As[rr + 4];
                a[mi][3] = As[rr + 8 * PAD_ + 4];
            }
            #pragma unroll
            for (int ni = 0; ni < 8; ni++) {
                int rr = (n0w + ni * 8 + r4) * PAD_ + kb + c4;
                b[ni][0] = Bs[rr];
                b[ni][1] = Bs[rr + 4];
            }
            #pragma unroll
            for (int mi = 0; mi < 4; mi++)
                #pragma unroll
                for (int ni = 0; ni < 8; ni++)
                    mma_tf32(acc[mi][ni], a[mi], b[ni]);
        }

        if (kt + 1 < KT) {
            stage((kt + 1) & 1);
            __syncthreads();
        }
    }

    #pragma unroll
    for (int mi = 0; mi < 4; mi++) {
        #pragma unroll
        for (int half_m = 0; half_m < 2; half_m++) {
            int m = m0 + m0w + mi * 16 + half_m * 8 + r4;
            int bb = m >> 11, ss = m & (S_ - 1);
            #pragma unroll
            for (int ni = 0; ni < 8; ni++) {
                int n = n0 + n0w + ni * 8 + c4 * 2;
                float2 o;
                o.x = acc[mi][ni][half_m * 2 + 0] * alpha;
                o.y = acc[mi][ni][half_m * 2 + 1] * alpha;
                if (MODE == 1) {
                    int h = n >> 7, dh = n & 127;
                    *(float2*)(C + (((size_t)bb * H_ + h) * S_ + ss) * DH_ + dh) = o;
                } else {
                    *(float2*)(C + (size_t)m * ldc + n) = o;
                }
            }
        }
    }
}

// ============================ gated reduce (V) =============================
__global__ __launch_bounds__(256) void vgate_kernel() {
    int idx = blockIdx.x * 256 + threadIdx.x;   // 4096*8*32
    int dh4 = idx & 31;
    int h = (idx >> 5) & 7;
    int t = idx >> 8;
    int b = t >> 11, s = t & (S_ - 1);
    const float* y = g_yall + (size_t)t * KEXP_ + h * 512 + dh4 * 4;
    const float* g = g_gv + (size_t)t * GE_ + h * 4;
    float4 acc = make_float4(0.f, 0.f, 0.f, 0.f);
    #pragma unroll
    for (int e = 0; e < 4; e++) {
        float ge = g[e];
        float4 ye = *(const float4*)(y + e * 128);
        acc.x += ge * ye.x; acc.y += ge * ye.y; acc.z += ge * ye.z; acc.w += ge * ye.w;
    }
    *(float4*)&g_v[(((size_t)b * H_ + h) * S_ + s) * DH_ + dh4 * 4] = acc;
}

// ============================ tf32 flash attention =========================
#define QP_ 132
#define VP_ 68
#define ATTN_SMEM ((128 * QP_ + 64 * QP_ + 128 * VP_ + 128 * VP_) * 4)

__global__ __launch_bounds__(256) void attn_tc_kernel() {
    extern __shared__ __align__(16) uint32_t asm_[];
    uint32_t* Qs = asm_;
    uint32_t* Ks = Qs + 128 * QP_;
    uint32_t* Vt = Ks + 64 * QP_;
    uint32_t* Ps = Vt + 128 * VP_;

    int bh = blockIdx.y;
    int q0 = blockIdx.x * 128;
    const float* Qg = g_q + (size_t)bh * S_ * DH_;
    const float* Kg = g_k + (size_t)bh * S_ * DH_;
    const float* Vg = g_v + (size_t)bh * S_ * DH_;

    int tid = threadIdx.x;
    int wid = tid >> 5;
    int lane = tid & 31;
    int r4 = lane >> 2, c4 = lane & 3;
    int m0w = wid * 16;

    for (int i = tid; i < 128 * 32; i += 256) {
        int r = i >> 5, c = (i & 31) * 4;
        float4 v = *(const float4*)(Qg + (size_t)(q0 + r) * DH_ + c);
        uint4 u = make_uint4(f2tf32(v.x), f2tf32(v.y), f2tf32(v.z), f2tf32(v.w));
        *(uint4*)&Qs[r * QP_ + c] = u;
    }

    float4 kreg[8], vreg[8];
    auto loadK = [&](int j0) {
        #pragma unroll
        for (int j = 0; j < 8; j++) {
            int i = tid + 256 * j;
            int r = i >> 5, c = (i & 31) * 4;
            kreg[j] = *(const float4*)(Kg + (size_t)(j0 + r) * DH_ + c);
        }
    };
    auto loadV = [&](int j0) {
        #pragma unroll
        for (int j = 0; j < 8; j++) {
            int i = tid + 256 * j;
            int r = i & 63, c = (i >> 6) * 4;
            vreg[j] = *(const float4*)(Vg + (size_t)(j0 + r) * DH_ + c);
        }
    };

    loadK(0);
    loadV(0);

    float o[16][4];
    #pragma unroll
    for (int ni = 0; ni < 16; ni++)
        #pragma unroll
        for (int c = 0; c < 4; c++) o[ni][c] = 0.f;
    float mA = -1e30f, mB = -1e30f, lA = 0.f, lB = 0.f;

    for (int j0 = 0; j0 < S_; j0 += 64) {
        __syncthreads();
        #pragma unroll
        for (int j = 0; j < 8; j++) {
            int i = tid + 256 * j;
            int r = i >> 5, c = (i & 31) * 4;
            uint4 u = make_uint4(f2tf32(kreg[j].x), f2tf32(kreg[j].y),
                                 f2tf32(kreg[j].z), f2tf32(kreg[j].w));
            *(uint4*)&Ks[r * QP_ + c] = u;
        }
        #pragma unroll
        for (int j = 0; j < 8; j++) {
            int i = tid + 256 * j;
            int r = i & 63, c = (i >> 6) * 4;
            Vt[(c + 0) * VP_ + r] = f2tf32(vreg[j].x);
            Vt[(c + 1) * VP_ + r] = f2tf32(vreg[j].y);
            Vt[(c + 2) * VP_ + r] = f2tf32(vreg[j].z);
            Vt[(c + 3) * VP_ + r] = f2tf32(vreg[j].w);
        }
        __syncthreads();

        bool more = (j0 + 64) < S_;
        if (more) loadK(j0 + 64);

        float sf[8][4];
        #pragma unroll
        for (int ni = 0; ni < 8; ni++)
            #pragma unroll
            for (int c = 0; c < 4; c++) sf[ni][c] = 0.f;

        #pragma unroll
        for (int ks = 0; ks < 16; ks++) {
            int kb = ks * 8;
            uint32_t a[4];
            int ar = (m0w + r4) * QP_ + kb + c4;
            a[0] = Qs[ar];
            a[1] = Qs[ar + 8 * QP_];
            a[2] = Qs[ar + 4];
            a[3] = Qs[ar + 8 * QP_ + 4];
            #pragma unroll
            for (int ni = 0; ni < 8; ni++) {
                uint32_t b[2];
                int br = (ni * 8 + r4) * QP_ + kb + c4;
                b[0] = Ks[br];
                b[1] = Ks[br + 4];
                mma_tf32(sf[ni], a, b);
            }
        }

        if (more) loadV(j0 + 64);

        float mxA = -1e30f, mxB = -1e30f;
        #pragma unroll
        for (int ni = 0; ni < 8; ni++) {
            mxA = fmaxf(mxA, fmaxf(sf[ni][0], sf[ni][1]));
            mxB = fmaxf(mxB, fmaxf(sf[ni][2], sf[ni][3]));
        }
        mxA = fmaxf(mxA, __shfl_xor_sync(0xffffffffu, mxA, 1));
        mxA = fmaxf(mxA, __shfl_xor_sync(0xffffffffu, mxA, 2));
        mxB = fmaxf(mxB, __shfl_xor_sync(0xffffffffu, mxB, 1));
        mxB = fmaxf(mxB, __shfl_xor_sync(0xffffffffu, mxB, 2));
        float mnA = fmaxf(mA, mxA), mnB = fmaxf(mB, mxB);
        float scA = __expf(mA - mnA), scB = __expf(mB - mnB);
        float sA = 0.f, sB = 0.f;
        int prA = (m0w + r4) * VP_;
        int prB = prA + 8 * VP_;
        #pragma unroll
        for (int ni = 0; ni < 8; ni++) {
            float e0 = __expf(sf[ni][0] - mnA);
            float e1 = __expf(sf[ni][1] - mnA);
            float e2 = __expf(sf[ni][2] - mnB);
            float e3 = __expf(sf[ni][3] - mnB);
            sA += e0 + e1; sB += e2 + e3;
            int cc = ni * 8 + c4 * 2;
            Ps[prA + cc] = f2tf32(e0); Ps[prA + cc + 1] = f2tf32(e1);
            Ps[prB + cc] = f2tf32(e2); Ps[prB + cc + 1] = f2tf32(e3);
        }
        sA += __shfl_xor_sync(0xffffffffu, sA, 1);
        sA += __shfl_xor_sync(0xffffffffu, sA, 2);
        sB += __shfl_xor_sync(0xffffffffu, sB, 1);
        sB += __shfl_xor_sync(0xffffffffu, sB, 2);
        lA = lA * scA + sA; lB = lB * scB + sB;
        mA = mnA; mB = mnB;
        #pragma unroll
        for (int ni = 0; ni < 16; ni++) {
            o[ni][0] *= scA; o[ni][1] *= scA;
            o[ni][2] *= scB; o[ni][3] *= scB;
        }
        __syncwarp();

        #pragma unroll
        for (int ks = 0; ks < 8; ks++) {
            int kb = ks * 8;
            uint32_t a[4];
            int ar = (m0w + r4) * VP_ + kb + c4;
            a[0] = Ps[ar];
            a[1] = Ps[ar + 8 * VP_];
            a[2] = Ps[ar + 4];
            a[3] = Ps[ar + 8 * VP_ + 4];
            #pragma unroll
            for (int ni = 0; ni < 16; ni++) {
                uint32_t b[2];
                int br = (ni * 8 + r4) * VP_ + kb + c4;
                b[0] = Vt[br];
                b[1] = Vt[br + 4];
                mma_tf32(o[ni], a, b);
            }
        }
    }

    float invA = 1.f / lA, invB = 1.f / lB;
    int rA = q0 + m0w + r4;
    float* OgA = g_res + (size_t)bh * S_ * DH_ + (size_t)rA * DH_;
    float* OgB = OgA + 8 * DH_;
    #pragma unroll
    for (int ni = 0; ni < 16; ni++) {
        int cc = ni * 8 + c4 * 2;
        float2 oa, ob;
        oa.x = o[ni][0] * invA; oa.y = o[ni][1] * invA;
        ob.x = o[ni][2] * invB; ob.y = o[ni][3] * invB;
        *(float2*)(OgA + cc) = oa;
        *(float2*)(OgB + cc) = ob;
    }
}

// ---------------------------------------------------------------------------
extern "C" void kernel_launch(void* const* d_in, const int* in_sizes, int n_in,
                              void* d_out, int out_size) {
    const float* q_src = (const float*)d_in[0];
    const float* k_src = (const float*)d_in[1];
    const float* v_src = (const float*)d_in[2];
    const float* Wq    = (const float*)d_in[3];
    const float* Wk    = (const float*)d_in[4];
    const float* Wv    = (const float*)d_in[5];
    const float* Wo    = (const float*)d_in[6];
    const float* sel_v = (const float*)d_in[7];
    const float* sel_o = (const float*)d_in[8];
    float* outp = (float*)d_out;

    cudaFuncSetAttribute(attn_tc_kernel, cudaFuncAttributeMaxDynamicSharedMemorySize, ATTN_SMEM);
    cudaFuncSetAttribute(gemm_tf32<0>, cudaFuncAttributeMaxDynamicSharedMemorySize, GSMEM_BYTES);
    cudaFuncSetAttribute(gemm_tf32<1>, cudaFuncAttributeMaxDynamicSharedMemorySize, GSMEM_BYTES);
    cudaFuncSetAttribute(gemm_tf32<2>, cudaFuncAttributeMaxDynamicSharedMemorySize, GSMEM_BYTES);

    float *gq, *gk, *gyall, *gwvT, *gwoT, *gres;
    cudaGetSymbolAddress((void**)&gq, g_q);
    cudaGetSymbolAddress((void**)&gk, g_k);
    cudaGetSymbolAddress((void**)&gyall, g_yall);
    cudaGetSymbolAddress((void**)&gwvT, g_wvT);
    cudaGetSymbolAddress((void**)&gwoT, g_woT);
    cudaGetSymbolAddress((void**)&gres, g_res);

    const float scale = 0.29730177875068026f;  // 128^-0.25

    router_kernel<<<TOK_, 256>>>(q_src, k_src, sel_v, sel_o);

    // Wv [H,E,D,DH] -> WvT [(h,e,dh), d]
    transpose_kernel<<<dim3(DH_ / 32, D_ / 32, GE_), dim3(32, 8)>>>(Wv, gwvT, D_, DH_);
    // Wo flat [(h,e,dh), o] -> WoT [o, (h,e,dh)]
    transpose_kernel<<<dim3(D_ / 32, KEXP_ / 32, 1), dim3(32, 8)>>>(Wo, gwoT, KEXP_, D_);

    // merged q/k projections: M=4096, N=1024, K=1024; z=0 -> q, z=1 -> k
    gemm_tf32<1><<<dim3(D_ / 256, TOK_ / 128, 2), 256, GSMEM_BYTES>>>(
        q_src, Wq, gq, D_, 0, scale, k_src, Wk, gk);

    // all-expert V: M=4096, N=4096, K=1024
    gemm_tf32<0><<<dim3(KEXP_ / 256, TOK_ / 128), 256, GSMEM_BYTES>>>(
        v_src, gwvT, gyall, D_, KEXP_, 1.0f, nullptr, nullptr, nullptr);
    vgate_kernel<<<TOK_ * H_ * 32 / 256, 256>>>();

    attn_tc_kernel<<<dim3(S_ / 128, B_ * H_), 256, ATTN_SMEM>>>();

    // out: M=4096, N=1024, K=4096, A = gated g_res expansion (MODE 2)
    gemm_tf32<2><<<dim3(D_ / 256, TOK_ / 128), 256, GSMEM_BYTES>>>(
        gres, gwoT, outp, KEXP_, D_, 1.0f, nullptr, nullptr, nullptr);
}

// round 8
// speedup vs baseline: 10.4295x; 1.2790x over previous
#include <cuda_runtime.h>
#include <math.h>
#include <stdint.h>

// ---------------------------------------------------------------------------
// SwitchHeadCore: B=2,S=2048,D=1024,H=8,E=4,K=2,DH=128
// All GEMM operands pre-converted to tf32 bits; GEMMs are 512-thread
// 128x256x32 cp.async 3-stage pipelined mma.sync kernels (16 warps, 32x64).
// ---------------------------------------------------------------------------

#define B_ 2
#define S_ 2048
#define D_ 1024
#define H_ 8
#define E_ 4
#define DH_ 128
#define TOK_ (B_ * S_)              // 4096
#define GE_ (H_ * E_)               // 32
#define KEXP_ 4096                  // H*E*DH

__device__ __align__(16) float g_q[TOK_ * D_];     // [B,H,S,DH] tf32 bits
__device__ __align__(16) float g_k[TOK_ * D_];     // tf32 bits
__device__ __align__(16) float g_v[TOK_ * D_];     // tf32 bits
__device__ __align__(16) float g_res[TOK_ * D_];   // fp32
__device__ float g_gv[TOK_ * GE_];
__device__ float g_go[TOK_ * GE_];
__device__ __align__(16) float g_yall[(size_t)TOK_ * KEXP_];  // fp32
__device__ __align__(16) float g_aexp[(size_t)TOK_ * KEXP_];  // tf32 bits
__device__ __align__(16) float g_wvT[(size_t)KEXP_ * D_];     // tf32 bits
__device__ __align__(16) float g_woT[(size_t)D_ * KEXP_];     // tf32 bits
__device__ __align__(16) float g_qc[TOK_ * D_];    // tf32 of q_src
__device__ __align__(16) float g_kc[TOK_ * D_];    // tf32 of k_src
__device__ __align__(16) float g_vc[TOK_ * D_];    // tf32 of v_src
__device__ __align__(16) float g_wqc[D_ * D_];     // tf32 of Wq
__device__ __align__(16) float g_wkc[D_ * D_];     // tf32 of Wk

// ============================ helpers ======================================
__device__ __forceinline__ uint32_t f2tf32(float f) {
    uint32_t u;
    asm("cvt.rna.tf32.f32 %0, %1;" : "=r"(u) : "f"(f));
    return u;
}
__device__ __forceinline__ float f2tf32f(float f) { return __uint_as_float(f2tf32(f)); }
__device__ __forceinline__ void mma_tf32(float* d, const uint32_t* a, const uint32_t* b) {
    asm volatile(
        "mma.sync.aligned.m16n8k8.row.col.f32.tf32.tf32.f32 "
        "{%0,%1,%2,%3}, {%4,%5,%6,%7}, {%8,%9}, {%0,%1,%2,%3};\n"
        : "+f"(d[0]), "+f"(d[1]), "+f"(d[2]), "+f"(d[3])
        : "r"(a[0]), "r"(a[1]), "r"(a[2]), "r"(a[3]), "r"(b[0]), "r"(b[1]));
}
__device__ __forceinline__ uint32_t smem_u32(const void* p) {
    uint32_t a;
    asm("{ .reg .u64 t; cvta.to.shared.u64 t, %1; cvt.u32.u64 %0, t; }" : "=r"(a) : "l"(p));
    return a;
}
#define CP16(dst, src) \
    asm volatile("cp.async.cg.shared.global [%0], [%1], 16;" :: "r"(dst), "l"(src))
#define CP_COMMIT() asm volatile("cp.async.commit_group;")
#define CP_WAIT1() asm volatile("cp.async.wait_group 1;")
#define CP_WAIT0() asm volatile("cp.async.wait_group 0;")

// ============================ router =======================================
__global__ void router_kernel(const float* __restrict__ q_src,
                              const float* __restrict__ k_src,
                              const float* __restrict__ sel_v,
                              const float* __restrict__ sel_o) {
    int t = blockIdx.x;
    int tid = threadIdx.x;
    __shared__ float xs[D_];
    __shared__ float sg[GE_];

    for (int r = 0; r < 2; r++) {
        const float* src = (r == 0) ? k_src : q_src;
        const float* sel = (r == 0) ? sel_v : sel_o;
        float* gout      = (r == 0) ? g_gv  : g_go;

        for (int i = tid; i < D_ / 4; i += blockDim.x)
            ((float4*)xs)[i] = ((const float4*)(src + (size_t)t * D_))[i];
        __syncthreads();

        int g = tid >> 3;
        int l8 = tid & 7;
        const float* w = sel + (size_t)g * D_;
        float sum = 0.f;
        for (int d = l8; d < D_; d += 8) sum += xs[d] * w[d];
        sum += __shfl_xor_sync(0xffffffffu, sum, 1);
        sum += __shfl_xor_sync(0xffffffffu, sum, 2);
        sum += __shfl_xor_sync(0xffffffffu, sum, 4);
        if (l8 == 0) sg[g] = 1.f / (1.f + __expf(-sum));
        __syncthreads();

        if (tid < H_) {
            int h = tid;
            float vals[4];
            #pragma unroll
            for (int e = 0; e < 4; e++) vals[e] = sg[h * 4 + e];
            int i1 = 0;
            #pragma unroll
            for (int e = 1; e < 4; e++) if (vals[e] > vals[i1]) i1 = e;
            int i2 = -1;
            #pragma unroll
            for (int e = 0; e < 4; e++) {
                if (e == i1) continue;
                if (i2 < 0 || vals[e] > vals[i2]) i2 = e;
            }
            #pragma unroll
            for (int e = 0; e < 4; e++)
                gout[(size_t)t * GE_ + h * 4 + e] = (e == i1 || e == i2) ? vals[e] : 0.f;
        }
        __syncthreads();
    }
}

// ============================ convert (fp32 -> tf32 bits) ==================
__global__ void conv_kernel(const float* __restrict__ src, float* __restrict__ dst, int n4) {
    int i = blockIdx.x * blockDim.x + threadIdx.x;
    if (i >= n4) return;
    float4 v = ((const float4*)src)[i];
    v.x = f2tf32f(v.x); v.y = f2tf32f(v.y); v.z = f2tf32f(v.z); v.w = f2tf32f(v.w);
    ((float4*)dst)[i] = v;
}

// ============================ transpose (emit tf32) ========================
__global__ void transpose_kernel(const float* __restrict__ src, float* __restrict__ dst,
                                 int R, int C) {
    __shared__ float tile[32][33];
    size_t zo = (size_t)blockIdx.z * R * C;
    src += zo; dst += zo;
    int r0 = blockIdx.y * 32, c0 = blockIdx.x * 32;
    int x = threadIdx.x, y = threadIdx.y;
    #pragma unroll
    for (int i = 0; i < 32; i += 8)
        tile[y + i][x] = src[(size_t)(r0 + y + i) * C + c0 + x];
    __syncthreads();
    #pragma unroll
    for (int i = 0; i < 32; i += 8)
        dst[(size_t)(c0 + y + i) * R + r0 + x] = f2tf32f(tile[x][y + i]);
}

// ============================ gated expand (O), tf32 out ===================
__global__ __launch_bounds__(256) void expand_kernel() {
    int idx = blockIdx.x * 256 + threadIdx.x;   // 4096*32*32
    int dh4 = idx & 31;
    int he = (idx >> 5) & 31;
    int t = idx >> 10;
    int h = he >> 2;
    int b = t >> 11, s = t & (S_ - 1);
    float g = g_go[(size_t)t * GE_ + he];
    float4 r = *(const float4*)&g_res[(((size_t)b * H_ + h) * S_ + s) * DH_ + dh4 * 4];
    r.x = f2tf32f(r.x * g); r.y = f2tf32f(r.y * g);
    r.z = f2tf32f(r.z * g); r.w = f2tf32f(r.w * g);
    *(float4*)&g_aexp[(size_t)t * KEXP_ + he * 128 + dh4 * 4] = r;
}

// ============================ gated reduce (V), tf32 out ===================
__global__ __launch_bounds__(256) void vgate_kernel() {
    int idx = blockIdx.x * 256 + threadIdx.x;   // 4096*8*32
    int dh4 = idx & 31;
    int h = (idx >> 5) & 7;
    int t = idx >> 8;
    int b = t >> 11, s = t & (S_ - 1);
    const float* y = g_yall + (size_t)t * KEXP_ + h * 512 + dh4 * 4;
    const float* g = g_gv + (size_t)t * GE_ + h * 4;
    float4 acc = make_float4(0.f, 0.f, 0.f, 0.f);
    #pragma unroll
    for (int e = 0; e < 4; e++) {
        float ge = g[e];
        float4 ye = *(const float4*)(y + e * 128);
        acc.x += ge * ye.x; acc.y += ge * ye.y; acc.z += ge * ye.z; acc.w += ge * ye.w;
    }
    acc.x = f2tf32f(acc.x); acc.y = f2tf32f(acc.y);
    acc.z = f2tf32f(acc.z); acc.w = f2tf32f(acc.w);
    *(float4*)&g_v[(((size_t)b * H_ + h) * S_ + s) * DH_ + dh4 * 4] = acc;
}

// ============================ tf32 mma GEMM (cp.async, 512 thr) ============
// C[M,N] = alpha * A[M,K] @ B[N,K]^T, A/B already tf32 bits.
// Block 128x256xBK32, 16 warps (4m x 4n), warp tile 32x64.  3-stage cp.async.
// MODE 0: row-major fp32 C.  MODE 1: qk merged (z picks), C [B,H,S,DH] tf32.
#define PAD_ 36
#define ABUF_ (128 * PAD_)
#define BBUF_ (256 * PAD_)
#define STG_W (ABUF_ + BBUF_)           // 13824 words per stage
#define GSMEM_BYTES (3 * STG_W * 4)     // 165888

template<int MODE>
__global__ __launch_bounds__(512) void gemm_tf32(const float* __restrict__ A,
                                                 const float* __restrict__ B,
                                                 float* __restrict__ C,
                                                 int Ktot, int ldc, float alpha,
                                                 const float* __restrict__ A2,
                                                 const float* __restrict__ B2,
                                                 float* __restrict__ C2) {
    extern __shared__ __align__(16) uint32_t dsm[];
    uint32_t sbase = smem_u32(dsm);

    int tid = threadIdx.x;
    int wid = tid >> 5;
    int lane = tid & 31;
    int m0 = blockIdx.y * 128, n0 = blockIdx.x * 256;
    int m0w = (wid >> 2) * 32, n0w = (wid & 3) * 64;

    if (MODE == 1 && blockIdx.z == 1) { A = A2; B = B2; C = C2; }

    // A tile: 128 rows x 32 floats = 1024 16B chunks; threads handle 2 each.
    int aS0 = tid, aS1 = tid + 512;
    int ar0 = aS0 >> 3, ac0 = (aS0 & 7) * 4;
    int ar1 = aS1 >> 3, ac1 = (aS1 & 7) * 4;
    const float* Asrc0 = A + (size_t)(m0 + ar0) * Ktot + ac0;
    const float* Asrc1 = A + (size_t)(m0 + ar1) * Ktot + ac1;
    uint32_t aDst0 = (uint32_t)(ar0 * PAD_ + ac0) * 4;
    uint32_t aDst1 = (uint32_t)(ar1 * PAD_ + ac1) * 4;
    // B tile: 256 rows x 32 floats = 2048 chunks; threads handle 4 each.
    int br[4], bc[4];
    const float* Bsrc[4];
    uint32_t bDst[4];
    #pragma unroll
    for (int j = 0; j < 4; j++) {
        int s = tid + 512 * j;
        br[j] = s >> 3; bc[j] = (s & 7) * 4;
        Bsrc[j] = B + (size_t)(n0 + br[j]) * Ktot + bc[j];
        bDst[j] = (uint32_t)(ABUF_ + br[j] * PAD_ + bc[j]) * 4;
    }

    float acc[2][8][4];
    #pragma unroll
    for (int i = 0; i < 2; i++)
        #pragma unroll
        for (int j = 0; j < 8; j++)
            #pragma unroll
            for (int c = 0; c < 4; c++) acc[i][j][c] = 0.f;

    int KT = Ktot >> 5;

    auto copyTile = [&](int kt, int stg) {
        uint32_t so = sbase + (uint32_t)(stg * STG_W * 4);
        int ko = kt * 32;
        CP16(so + aDst0, Asrc0 + ko);
        CP16(so + aDst1, Asrc1 + ko);
        #pragma unroll
        for (int j = 0; j < 4; j++)
            CP16(so + bDst[j], Bsrc[j] + ko);
        CP_COMMIT();
    };

    copyTile(0, 0);
    copyTile(1, 1);

    int r4 = lane >> 2, c4 = lane & 3;

    for (int kt = 0; kt < KT; kt++) {
        if (kt + 1 < KT) CP_WAIT1(); else CP_WAIT0();
        __syncthreads();

        uint32_t* As = dsm + (kt % 3) * STG_W;
        uint32_t* Bs = As + ABUF_;
        #pragma unroll
        for (int ks = 0; ks < 4; ks++) {
            int kb = ks * 8;
            uint32_t a[2][4], b[8][2];
            #pragma unroll
            for (int mi = 0; mi < 2; mi++) {
                int rr = (m0w + mi * 16 + r4) * PAD_ + kb + c4;
                a[mi][0] = As[rr];
                a[mi][1] = As[rr + 8 * PAD_];
                a[mi][2] = As[rr + 4];
                a[mi][3] = As[rr + 8 * PAD_ + 4];
            }
            #pragma unroll
            for (int ni = 0; ni < 8; ni++) {
                int rr = (n0w + ni * 8 + r4) * PAD_ + kb + c4;
                b[ni][0] = Bs[rr];
                b[ni][1] = Bs[rr + 4];
            }
            #pragma unroll
            for (int mi = 0; mi < 2; mi++)
                #pragma unroll
                for (int ni = 0; ni < 8; ni++)
                    mma_tf32(acc[mi][ni], a[mi], b[ni]);
        }

        if (kt + 2 < KT) copyTile(kt + 2, (kt + 2) % 3);
    }

    #pragma unroll
    for (int mi = 0; mi < 2; mi++) {
        #pragma unroll
        for (int half_m = 0; half_m < 2; half_m++) {
            int m = m0 + m0w + mi * 16 + half_m * 8 + r4;
            int bb = m >> 11, ss = m & (S_ - 1);
            #pragma unroll
            for (int ni = 0; ni < 8; ni++) {
                int n = n0 + n0w + ni * 8 + c4 * 2;
                float2 o;
                o.x = acc[mi][ni][half_m * 2 + 0] * alpha;
                o.y = acc[mi][ni][half_m * 2 + 1] * alpha;
                if (MODE == 1) {
                    o.x = f2tf32f(o.x);
                    o.y = f2tf32f(o.y);
                    int h = n >> 7, dh = n & 127;
                    *(float2*)(C + (((size_t)bb * H_ + h) * S_ + ss) * DH_ + dh) = o;
                } else {
                    *(float2*)(C + (size_t)m * ldc + n) = o;
                }
            }
        }
    }
}

// ============================ tf32 flash attention =========================
// q tile 128 (8 warps x 16 rows), kv tile 64; q/k/v already tf32 bits.
#define QP_ 132
#define VP_ 68
#define ATTN_SMEM ((128 * QP_ + 64 * QP_ + 128 * VP_ + 128 * VP_) * 4)

__global__ __launch_bounds__(256) void attn_tc_kernel() {
    extern __shared__ __align__(16) uint32_t asm_[];
    uint32_t* Qs = asm_;
    uint32_t* Ks = Qs + 128 * QP_;
    uint32_t* Vt = Ks + 64 * QP_;
    uint32_t* Ps = Vt + 128 * VP_;

    int bh = blockIdx.y;
    int q0 = blockIdx.x * 128;
    const float* Qg = g_q + (size_t)bh * S_ * DH_;
    const float* Kg = g_k + (size_t)bh * S_ * DH_;
    const float* Vg = g_v + (size_t)bh * S_ * DH_;

    int tid = threadIdx.x;
    int wid = tid >> 5;
    int lane = tid & 31;
    int r4 = lane >> 2, c4 = lane & 3;
    int m0w = wid * 16;

    for (int i = tid; i < 128 * 32; i += 256) {
        int r = i >> 5, c = (i & 31) * 4;
        *(uint4*)&Qs[r * QP_ + c] = *(const uint4*)(Qg + (size_t)(q0 + r) * DH_ + c);
    }

    float4 kreg[8], vreg[8];
    auto loadK = [&](int j0) {
        #pragma unroll
        for (int j = 0; j < 8; j++) {
            int i = tid + 256 * j;
            int r = i >> 5, c = (i & 31) * 4;
            kreg[j] = *(const float4*)(Kg + (size_t)(j0 + r) * DH_ + c);
        }
    };
    auto loadV = [&](int j0) {
        #pragma unroll
        for (int j = 0; j < 8; j++) {
            int i = tid + 256 * j;
            int r = i & 63, c = (i >> 6) * 4;
            vreg[j] = *(const float4*)(Vg + (size_t)(j0 + r) * DH_ + c);
        }
    };

    loadK(0);
    loadV(0);

    float o[16][4];
    #pragma unroll
    for (int ni = 0; ni < 16; ni++)
        #pragma unroll
        for (int c = 0; c < 4; c++) o[ni][c] = 0.f;
    float mA = -1e30f, mB = -1e30f, lA = 0.f, lB = 0.f;

    for (int j0 = 0; j0 < S_; j0 += 64) {
        __syncthreads();
        #pragma unroll
        for (int j = 0; j < 8; j++) {
            int i = tid + 256 * j;
            int r = i >> 5, c = (i & 31) * 4;
            *(uint4*)&Ks[r * QP_ + c] = *(const uint4*)&kreg[j];
        }
        #pragma unroll
        for (int j = 0; j < 8; j++) {
            int i = tid + 256 * j;
            int r = i & 63, c = (i >> 6) * 4;
            Vt[(c + 0) * VP_ + r] = __float_as_uint(vreg[j].x);
            Vt[(c + 1) * VP_ + r] = __float_as_uint(vreg[j].y);
            Vt[(c + 2) * VP_ + r] = __float_as_uint(vreg[j].z);
            Vt[(c + 3) * VP_ + r] = __float_as_uint(vreg[j].w);
        }
        __syncthreads();

        bool more = (j0 + 64) < S_;
        if (more) loadK(j0 + 64);

        float sf[8][4];
        #pragma unroll
        for (int ni = 0; ni < 8; ni++)
            #pragma unroll
            for (int c = 0; c < 4; c++) sf[ni][c] = 0.f;

        #pragma unroll
        for (int ks = 0; ks < 16; ks++) {
            int kb = ks * 8;
            uint32_t a[4];
            int ar = (m0w + r4) * QP_ + kb + c4;
            a[0] = Qs[ar];
            a[1] = Qs[ar + 8 * QP_];
            a[2] = Qs[ar + 4];
            a[3] = Qs[ar + 8 * QP_ + 4];
            #pragma unroll
            for (int ni = 0; ni < 8; ni++) {
                uint32_t b[2];
                int br = (ni * 8 + r4) * QP_ + kb + c4;
                b[0] = Ks[br];
                b[1] = Ks[br + 4];
                mma_tf32(sf[ni], a, b);
            }
        }

        if (more) loadV(j0 + 64);

        float mxA = -1e30f, mxB = -1e30f;
        #pragma unroll
        for (int ni = 0; ni < 8; ni++) {
            mxA = fmaxf(mxA, fmaxf(sf[ni][0], sf[ni][1]));
            mxB = fmaxf(mxB, fmaxf(sf[ni][2], sf[ni][3]));
        }
        mxA = fmaxf(mxA, __shfl_xor_sync(0xffffffffu, mxA, 1));
        mxA = fmaxf(mxA, __shfl_xor_sync(0xffffffffu, mxA, 2));
        mxB = fmaxf(mxB, __shfl_xor_sync(0xffffffffu, mxB, 1));
        mxB = fmaxf(mxB, __shfl_xor_sync(0xffffffffu, mxB, 2));
        float mnA = fmaxf(mA, mxA), mnB = fmaxf(mB, mxB);
        float scA = __expf(mA - mnA), scB = __expf(mB - mnB);
        float sA = 0.f, sB = 0.f;
        int prA = (m0w + r4) * VP_;
        int prB = prA + 8 * VP_;
        #pragma unroll
        for (int ni = 0; ni < 8; ni++) {
            float e0 = __expf(sf[ni][0] - mnA);
            float e1 = __expf(sf[ni][1] - mnA);
            float e2 = __expf(sf[ni][2] - mnB);
            float e3 = __expf(sf[ni][3] - mnB);
            sA += e0 + e1; sB += e2 + e3;
            int cc = ni * 8 + c4 * 2;
            Ps[prA + cc] = f2tf32(e0); Ps[prA + cc + 1] = f2tf32(e1);
            Ps[prB + cc] = f2tf32(e2); Ps[prB + cc + 1] = f2tf32(e3);
        }
        sA += __shfl_xor_sync(0xffffffffu, sA, 1);
        sA += __shfl_xor_sync(0xffffffffu, sA, 2);
        sB += __shfl_xor_sync(0xffffffffu, sB, 1);
        sB += __shfl_xor_sync(0xffffffffu, sB, 2);
        lA = lA * scA + sA; lB = lB * scB + sB;
        mA = mnA; mB = mnB;
        #pragma unroll
        for (int ni = 0; ni < 16; ni++) {
            o[ni][0] *= scA; o[ni][1] *= scA;
            o[ni][2] *= scB; o[ni][3] *= scB;
        }
        __syncwarp();

        #pragma unroll
        for (int ks = 0; ks < 8; ks++) {
            int kb = ks * 8;
            uint32_t a[4];
            int ar = (m0w + r4) * VP_ + kb + c4;
            a[0] = Ps[ar];
            a[1] = Ps[ar + 8 * VP_];
            a[2] = Ps[ar + 4];
            a[3] = Ps[ar + 8 * VP_ + 4];
            #pragma unroll
            for (int ni = 0; ni < 16; ni++) {
                uint32_t b[2];
                int br = (ni * 8 + r4) * VP_ + kb + c4;
                b[0] = Vt[br];
                b[1] = Vt[br + 4];
                mma_tf32(o[ni], a, b);
            }
        }
    }

    float invA = 1.f / lA, invB = 1.f / lB;
    int rA = q0 + m0w + r4;
    float* OgA = g_res + (size_t)bh * S_ * DH_ + (size_t)rA * DH_;
    float* OgB = OgA + 8 * DH_;
    #pragma unroll
    for (int ni = 0; ni < 16; ni++) {
        int cc = ni * 8 + c4 * 2;
        float2 oa, ob;
        oa.x = o[ni][0] * invA; oa.y = o[ni][1] * invA;
        ob.x = o[ni][2] * invB; ob.y = o[ni][3] * invB;
        *(float2*)(OgA + cc) = oa;
        *(float2*)(OgB + cc) = ob;
    }
}

// ---------------------------------------------------------------------------
extern "C" void kernel_launch(void* const* d_in, const int* in_sizes, int n_in,
                              void* d_out, int out_size) {
    const float* q_src = (const float*)d_in[0];
    const float* k_src = (const float*)d_in[1];
    const float* v_src = (const float*)d_in[2];
    const float* Wq    = (const float*)d_in[3];
    const float* Wk    = (const float*)d_in[4];
    const float* Wv    = (const float*)d_in[5];
    const float* Wo    = (const float*)d_in[6];
    const float* sel_v = (const float*)d_in[7];
    const float* sel_o = (const float*)d_in[8];
    float* outp = (float*)d_out;

    cudaFuncSetAttribute(attn_tc_kernel, cudaFuncAttributeMaxDynamicSharedMemorySize, ATTN_SMEM);
    cudaFuncSetAttribute(gemm_tf32<0>, cudaFuncAttributeMaxDynamicSharedMemorySize, GSMEM_BYTES);
    cudaFuncSetAttribute(gemm_tf32<1>, cudaFuncAttributeMaxDynamicSharedMemorySize, GSMEM_BYTES);

    float *gq, *gk, *gyall, *gaexp, *gwvT, *gwoT;
    float *gqc, *gkc, *gvc, *gwqc, *gwkc;
    cudaGetSymbolAddress((void**)&gq, g_q);
    cudaGetSymbolAddress((void**)&gk, g_k);
    cudaGetSymbolAddress((void**)&gyall, g_yall);
    cudaGetSymbolAddress((void**)&gaexp, g_aexp);
    cudaGetSymbolAddress((void**)&gwvT, g_wvT);
    cudaGetSymbolAddress((void**)&gwoT, g_woT);
    cudaGetSymbolAddress((void**)&gqc, g_qc);
    cudaGetSymbolAddress((void**)&gkc, g_kc);
    cudaGetSymbolAddress((void**)&gvc, g_vc);
    cudaGetSymbolAddress((void**)&gwqc, g_wqc);
    cudaGetSymbolAddress((void**)&gwkc, g_wkc);

    const float scale = 0.29730177875068026f;  // 128^-0.25

    router_kernel<<<TOK_, 256>>>(q_src, k_src, sel_v, sel_o);

    // convert sources and Wq/Wk to tf32 bits
    int n4a = TOK_ * D_ / 4, n4w = D_ * D_ / 4;
    conv_kernel<<<(n4a + 255) / 256, 256>>>(q_src, gqc, n4a);
    conv_kernel<<<(n4a + 255) / 256, 256>>>(k_src, gkc, n4a);
    conv_kernel<<<(n4a + 255) / 256, 256>>>(v_src, gvc, n4a);
    conv_kernel<<<(n4w + 255) / 256, 256>>>(Wq, gwqc, n4w);
    conv_kernel<<<(n4w + 255) / 256, 256>>>(Wk, gwkc, n4w);

    // Wv [H,E,D,DH] -> WvT [(h,e,dh), d]  (tf32); Wo -> WoT [o,(h,e,dh)] (tf32)
    transpose_kernel<<<dim3(DH_ / 32, D_ / 32, GE_), dim3(32, 8)>>>(Wv, gwvT, D_, DH_);
    transpose_kernel<<<dim3(D_ / 32, KEXP_ / 32, 1), dim3(32, 8)>>>(Wo, gwoT, KEXP_, D_);

    // merged q/k projections: M=4096, N=1024, K=1024; z=0 -> q, z=1 -> k
    gemm_tf32<1><<<dim3(D_ / 256, TOK_ / 128, 2), 512, GSMEM_BYTES>>>(
        gqc, gwqc, gq, D_, 0, scale, gkc, gwkc, gk);

    // all-expert V: M=4096, N=4096, K=1024
    gemm_tf32<0><<<dim3(KEXP_ / 256, TOK_ / 128), 512, GSMEM_BYTES>>>(
        gvc, gwvT, gyall, D_, KEXP_, 1.0f, nullptr, nullptr, nullptr);
    vgate_kernel<<<TOK_ * H_ * 32 / 256, 256>>>();

    attn_tc_kernel<<<dim3(S_ / 128, B_ * H_), 256, ATTN_SMEM>>>();

    // gated expansion (tf32) then out: M=4096, N=1024, K=4096
    expand_kernel<<<TOK_ * GE_ * 32 / 256, 256>>>();
    gemm_tf32<0><<<dim3(D_ / 256, TOK_ / 128), 512, GSMEM_BYTES>>>(
        gaexp, gwoT, outp, KEXP_, D_, 1.0f, nullptr, nullptr, nullptr);
}